// round 16
// baseline (speedup 1.0000x reference)
#include <cuda_runtime.h>
#include <cuda_bf16.h>
#include <mma.h>
#include <math.h>
#include <stdint.h>

using namespace nvcuda;

#define BB 4
#define CC 64
#define HH_ 256
#define WW_ 256
#define HS 128
#define WS 128
#define NSUB (BB*CC*HS*WS)
#define NTOK (BB*HS*WS)
#define PIX  (HS*WS)

__device__ float g_ll[NSUB];
__device__ float g_lh[NSUB];
__device__ float g_hl[NSUB];
__device__ float g_hh[NSUB];
__device__ float g_o1[BB*32*HH_*WW_];
__device__ float g_gx[3*NTOK];
__device__ float g_gy[3*NTOK];
__device__ float g_dlh[NSUB];
__device__ float g_dhl[NSUB];
__device__ float g_dhh[NSUB];
__device__ float g_fs[4*NSUB];   /* processed subbands, tile layout */
__device__ float g_z2[NSUB];
/* pre-split bf16 weights */
__device__ __nv_bfloat16 g_w1hi[16384], g_w1lo[16384];
__device__ __nv_bfloat16 g_w2hi[16384], g_w2lo[16384];
__device__ __nv_bfloat16 g_cwhi[147456], g_cwlo[147456];
__device__ __nv_bfloat16 g_owhi[18432],  g_owlo[18432];
__device__ __nv_bfloat16 g_fwhi[16384],  g_fwlo[16384];

__device__ __forceinline__ float fast_gelu(float v) {
    float s = v * 0.70710678118654752440f;
    float a = fabsf(s);
    float t = __fdividef(1.0f, 1.0f + 0.3275911f * a);
    float e = __expf(-a * a);
    float p = t * (0.254829592f + t * (-0.284496736f + t * (1.421413741f +
              t * (-1.453152027f + t * 1.061405429f))));
    float er = copysignf(1.0f - p * e, s);
    return 0.5f * v * (1.0f + er);
}

__device__ __forceinline__ uint32_t pack_hi2(uint32_t b0, uint32_t b1) {
    uint32_t r;
    asm("prmt.b32 %0, %1, %2, 0x7632;" : "=r"(r) : "r"(b0), "r"(b1));
    return r;
}
__device__ __forceinline__ uint32_t pack_lo2(float v0, uint32_t b0, float v1, uint32_t b1) {
    float l0 = v0 - __uint_as_float(b0 & 0xFFFF0000u);
    float l1 = v1 - __uint_as_float(b1 & 0xFFFF0000u);
    uint32_t r;
    asm("cvt.rn.bf16x2.f32 %0, %1, %2;" : "=r"(r) : "f"(l1), "f"(l0));
    return r;
}

/* ---------------- K-prep ---------------- */
__global__ void k_prep(const float* __restrict__ w1, const float* __restrict__ w2,
                       const float* __restrict__ wll, const float* __restrict__ wlh,
                       const float* __restrict__ whl, const float* __restrict__ whh,
                       const float* __restrict__ ow1, const float* __restrict__ fw) {
    int i = blockIdx.x * blockDim.x + threadIdx.x;
    float v; __nv_bfloat16* dh; __nv_bfloat16* dl; int d;
    if (i < 16384) { v = w1[i]; dh = g_w1hi; dl = g_w1lo; d = i; }
    else if (i < 32768) { d = i - 16384; v = w2[d]; dh = g_w2hi; dl = g_w2lo; }
    else if (i < 180224) {
        int j = i - 32768;
        int sub = j / 36864, r = j % 36864;
        int kk = r >> 12, ic = (r >> 6) & 63, oc = r & 63;
        const float* ws = (sub == 0) ? wll : (sub == 1) ? wlh : (sub == 2) ? whl : whh;
        v = ws[(oc * 64 + ic) * 9 + kk];
        dh = g_cwhi; dl = g_cwlo; d = j;
    } else if (i < 198656) {
        int j = i - 180224;
        int kk = j >> 11, ic = (j >> 5) & 63, oc = j & 31;
        v = ow1[(oc * 64 + ic) * 9 + kk];
        dh = g_owhi; dl = g_owlo; d = j;
    } else if (i < 215040) {
        int j = i - 198656;
        int k = j >> 6, n = j & 63;
        v = fw[n * 256 + k];
        dh = g_fwhi; dl = g_fwlo; d = j;
    } else return;
    __nv_bfloat16 hi = __float2bfloat16(v);
    dh[d] = hi;
    dl[d] = __float2bfloat16(v - __bfloat162float(hi));
}

/* ---------------- K1: Haar DWT ---------------- */
__global__ void k_dwt(const float* __restrict__ R) {
    int idx = blockIdx.x * blockDim.x + threadIdx.x;
    if (idx >= NSUB) return;
    int x = idx & (WS - 1);
    int y = (idx >> 7) & (HS - 1);
    int bc = idx >> 14;
    const float* p = R + ((long)bc * HH_ + 2 * y) * WW_ + 2 * x;
    float2 r0 = *reinterpret_cast<const float2*>(p);
    float2 r1 = *reinterpret_cast<const float2*>(p + WW_);
    const float s = 0.70710678118654752440f;
    float xl0 = (r0.x + r0.y) * s, xh0 = (r0.y - r0.x) * s;
    float xl1 = (r1.x + r1.y) * s, xh1 = (r1.y - r1.x) * s;
    g_ll[idx] = (xl0 + xl1) * s;
    g_lh[idx] = (xl1 - xl0) * s;
    g_hl[idx] = (xh0 + xh1) * s;
    g_hh[idx] = (xh1 - xh0) * s;
}

/* slab smem for off1: 4 rows x 68 x, ic-stride 72, hi+lo */
#define S2_H 0
#define S2_L 39168
#define S2_B 78336
#define S2_SMEM 78592

/* ====== K2: off conv1 wmma (64->32)+gelu; 2-row CTAs; 2-way K-split ==== */
__global__ void __launch_bounds__(256, 2)
k_off1_mma(const float* __restrict__ R, const float* __restrict__ bias) {
    extern __shared__ char sb[];
    __nv_bfloat16* slH = (__nv_bfloat16*)(sb + S2_H);
    __nv_bfloat16* slL = (__nv_bfloat16*)(sb + S2_L);
    float* bs = (float*)(sb + S2_B);
    int tid = threadIdx.x, wid = tid >> 5;
    int r = blockIdx.x;
    int xq = r & 3, yp = (r >> 2) & 127, b = r >> 9;
    int x0 = xq * 64, y0 = yp * 2;
    if (tid < 32) bs[tid] = bias[tid];
    const float* inb = R + (long)b * 64 * 65536;
    for (int p = tid; p < 8704; p += 256) {
        int xs = p % 68, rest = p / 68;
        int icp = rest & 31, row = rest >> 5;
        int ic = icp * 2;
        int yy = y0 + row - 1, gx = x0 + xs - 1;
        float v0 = 0.f, v1 = 0.f;
        if ((unsigned)yy < 256 && (unsigned)gx < 256) {
            v0 = inb[ic * 65536 + yy * 256 + gx];
            v1 = inb[(ic + 1) * 65536 + yy * 256 + gx];
        }
        uint32_t b0 = __float_as_uint(v0), b1 = __float_as_uint(v1);
        int ad = (row * 68 + xs) * 72 + ic;
        *(uint32_t*)(slH + ad) = pack_hi2(b0, b1);
        *(uint32_t*)(slL + ad) = pack_lo2(v0, b0, v1, b1);
    }
    __syncthreads();
    int wg = wid >> 2, ws = wid & 3;
    int m0 = ws * 32;
    wmma::fragment<wmma::accumulator, 16, 16, 16, float> acc[2][2];
#pragma unroll
    for (int i = 0; i < 2; i++)
#pragma unroll
        for (int j = 0; j < 2; j++) wmma::fill_fragment(acc[i][j], 0.f);
    for (int it = 0; it < 18; it++) {
        int idx = wg * 18 + it;
        int kk = idx >> 2, kt = idx & 3;
        int ky = kk / 3, kx = kk % 3;
        wmma::fragment<wmma::matrix_a, 16, 16, 16, __nv_bfloat16, wmma::row_major> ah[2], al[2];
#pragma unroll
        for (int i = 0; i < 2; i++) {
            int m = m0 + i * 16;
            int base = (((m >> 6) + ky) * 68 + (m & 63) + kx) * 72 + kt * 16;
            wmma::load_matrix_sync(ah[i], slH + base, 72);
            wmma::load_matrix_sync(al[i], slL + base, 72);
        }
        wmma::fragment<wmma::matrix_b, 16, 16, 16, __nv_bfloat16, wmma::row_major> bf[2];
#pragma unroll
        for (int j = 0; j < 2; j++)
            wmma::load_matrix_sync(bf[j], g_owhi + kk * 2048 + kt * 512 + j * 16, 32);
#pragma unroll
        for (int i = 0; i < 2; i++)
#pragma unroll
            for (int j = 0; j < 2; j++) {
                wmma::mma_sync(acc[i][j], ah[i], bf[j], acc[i][j]);
                wmma::mma_sync(acc[i][j], al[i], bf[j], acc[i][j]);
            }
#pragma unroll
        for (int j = 0; j < 2; j++)
            wmma::load_matrix_sync(bf[j], g_owlo + kk * 2048 + kt * 512 + j * 16, 32);
#pragma unroll
        for (int i = 0; i < 2; i++)
#pragma unroll
            for (int j = 0; j < 2; j++)
                wmma::mma_sync(acc[i][j], ah[i], bf[j], acc[i][j]);
    }
    __syncthreads();
    float* HFp = (float*)sb + wg * 4608;
#pragma unroll
    for (int i = 0; i < 2; i++)
#pragma unroll
        for (int j = 0; j < 2; j++)
            wmma::store_matrix_sync(HFp + (m0 + i * 16) * 36 + j * 16, acc[i][j], 36,
                                    wmma::mem_row_major);
    __syncthreads();
    float* HF = (float*)sb;
    float* op = g_o1 + (long)b * 32 * 65536 + y0 * 256 + x0;
    for (int e = tid; e < 4096; e += 256) {
        int dy = e >> 11, oc = (e >> 6) & 31, xx = e & 63;
        int t = dy * 64 + xx;
        op[oc * 65536 + dy * 256 + xx] =
            fast_gelu(HF[t * 36 + oc] + HF[4608 + t * 36 + oc] + bs[oc]);
    }
}

/* ------- K3: offset conv2 (32->6) + avgpool + coord precompute ------- */
__device__ __forceinline__ float reflectf(float v) {
    v = fabsf(v);
    v = fmodf(v, 254.0f);
    return v > 127.0f ? 254.0f - v : v;
}

__global__ void k_off2(const float* __restrict__ w, const float* __restrict__ bias) {
    __shared__ float sw[32 * 9 * 6];
    __shared__ float sb[6];
    for (int i = threadIdx.x; i < 32 * 9 * 6; i += blockDim.x) {
        int oc = i % 6; int r = i / 6; int ic = r / 9; int k = r % 9;
        sw[i] = w[(oc * 32 + ic) * 9 + k];
    }
    if (threadIdx.x < 6) sb[threadIdx.x] = bias[threadIdx.x];
    __syncthreads();
    int t = blockIdx.x * blockDim.x + threadIdx.x;
    if (t >= NTOK) return;
    int x = t & 127, y = (t >> 7) & 127, b = t >> 14;
    float s6[6] = {0, 0, 0, 0, 0, 0};
    const float* inb = g_o1 + (long)b * 32 * HH_ * WW_;
    for (int ic = 0; ic < 32; ic++) {
        const float* p = inb + ic * HH_ * WW_;
        float v[4][4];
#pragma unroll
        for (int r = 0; r < 4; r++) {
            int yy = 2 * y - 1 + r;
#pragma unroll
            for (int cc = 0; cc < 4; cc++) {
                int xx = 2 * x - 1 + cc;
                v[r][cc] = ((unsigned)yy < HH_ && (unsigned)xx < WW_) ? p[yy * WW_ + xx] : 0.f;
            }
        }
        const float* pw = sw + ic * 9 * 6;
#pragma unroll
        for (int k = 0; k < 9; k++) {
            int ky = k / 3, kx = k % 3;
            float vs = v[ky][kx] + v[ky][kx + 1] + v[ky + 1][kx] + v[ky + 1][kx + 1];
#pragma unroll
            for (int oc = 0; oc < 6; oc++) s6[oc] += vs * pw[k * 6 + oc];
        }
    }
#pragma unroll
    for (int s = 0; s < 3; s++) {
        float ox = tanhf(sb[2 * s] + 0.25f * s6[2 * s]) * 0.25f;
        float oy = tanhf(sb[2 * s + 1] + 0.25f * s6[2 * s + 1]) * 0.25f;
        float gx = -1.0f + 2.0f * x / 127.0f + ox;
        float gy = -1.0f + 2.0f * y / 127.0f + oy;
        g_gx[s * NTOK + t] = reflectf((gx + 1.0f) * 0.5f * 127.0f);
        g_gy[s * NTOK + t] = reflectf((gy + 1.0f) * 0.5f * 127.0f);
    }
}

/* ---------------- K4: deform, 8 channels/thread ---------------- */
__global__ void k_deform() {
    int g = blockIdx.x * 256 + threadIdx.x;
    int s = blockIdx.y;
    int pix = g >> 3, cg = g & 7;
    int b = pix >> 14, p = pix & 16383;
    const float* src = (s == 0) ? g_lh : (s == 1) ? g_hl : g_hh;
    float* dst = (s == 0) ? g_dlh : (s == 1) ? g_dhl : g_dhh;
    float ix = g_gx[s * NTOK + pix];
    float iy = g_gy[s * NTOK + pix];
    float x0f = floorf(ix), y0f = floorf(iy);
    float wx = ix - x0f, wy = iy - y0f;
    int x0 = min(max((int)x0f, 0), 127), x1 = min(x0 + 1, 127);
    int y0 = min(max((int)y0f, 0), 127), y1 = min(y0 + 1, 127);
    float w00 = (1 - wx) * (1 - wy), w01 = wx * (1 - wy);
    float w10 = (1 - wx) * wy, w11 = wx * wy;
    int i00 = y0 * WS + x0, i01 = y0 * WS + x1, i10 = y1 * WS + x0, i11 = y1 * WS + x1;
    const float* sp = src + ((long)(b * CC + cg * 8)) * PIX;
    float* dp = dst + ((long)(b * CC + cg * 8)) * PIX + p;
#pragma unroll
    for (int j = 0; j < 8; j++) {
        const float* pc = sp + j * PIX;
        dp[j * PIX] = __ldg(pc + i00) * w00 + __ldg(pc + i01) * w01 +
                      __ldg(pc + i10) * w10 + __ldg(pc + i11) * w11;
    }
}

/* ====== K5: FUSED subband conv3x3 + LN + FFN + residual ====== */
/* smem layout (bytes):
   conv phase: slab hi 0..39168, lo 39168..78336; HF partials overlay slab
   consts at 78336 (bias 256 | lnw 256 | lnb 256 | b1 1024 | b2 256)
   z (fp32, ld 65) at 80640..113920
   ffn phase: Xhi 0 (ld72), Xlo 18432, HF fp32 ld72 at 36864 (A2hi@36864, A2lo@55296) */
#define CF_CONST 78336
#define CF_Z     80640
#define CF_SMEM  113920

__global__ void __launch_bounds__(256, 2)
k_conv_ffn(int sub0, const float* __restrict__ bll, const float* __restrict__ blh,
           const float* __restrict__ bhl, const float* __restrict__ bhh,
           const float* __restrict__ lnw, const float* __restrict__ lnb,
           const float* __restrict__ b1p, const float* __restrict__ b2p) {
    extern __shared__ char sb[];
    __nv_bfloat16* slH = (__nv_bfloat16*)sb;
    __nv_bfloat16* slL = (__nv_bfloat16*)(sb + 39168);
    float* bs   = (float*)(sb + CF_CONST);
    float* lnws = bs + 64;
    float* lnbs = lnws + 64;
    float* b1s  = lnbs + 64;
    float* b2s  = b1s + 256;
    float* Z    = (float*)(sb + CF_Z);
    int tid = threadIdx.x, wid = tid >> 5;
    int sub = sub0 + (blockIdx.x >> 9);
    int r = blockIdx.x & 511;
    int xh = r & 1, yp = (r >> 1) & 63, b = r >> 7;
    int x0 = xh * 64, y0 = yp * 2;
    const float* bias = (sub == 0) ? bll : (sub == 1) ? blh : (sub == 2) ? bhl : bhh;
    if (tid < 64) {
        bs[tid] = bias[tid];
        lnws[tid] = lnw[tid];
        lnbs[tid] = lnb[tid];
        b2s[tid] = b2p[tid];
    }
    if (tid < 256) b1s[tid] = b1p[tid];
    const float* in = (sub == 0) ? g_ll : (sub == 1) ? g_dlh : (sub == 2) ? g_dhl : g_dhh;
    const float* inb = in + (long)b * CC * PIX;
    for (int p = tid; p < 8704; p += 256) {
        int xs = p % 68, rest = p / 68;
        int icp = rest & 31, row = rest >> 5;
        int ic = icp * 2;
        int yy = y0 + row - 1, gx = x0 + xs - 1;
        float v0 = 0.f, v1 = 0.f;
        if ((unsigned)yy < 128 && (unsigned)gx < 128) {
            v0 = inb[ic * PIX + yy * 128 + gx];
            v1 = inb[(ic + 1) * PIX + yy * 128 + gx];
        }
        uint32_t b0 = __float_as_uint(v0), b1 = __float_as_uint(v1);
        int ad = (row * 68 + xs) * 72 + ic;
        *(uint32_t*)(slH + ad) = pack_hi2(b0, b1);
        *(uint32_t*)(slL + ad) = pack_lo2(v0, b0, v1, b1);
    }
    __syncthreads();
    /* conv MMA: 2 K-groups x 4 M-positions, 32M x 64N per warp */
    {
        int wg = wid >> 2, ws = wid & 3;
        int m0 = ws * 32;
        const __nv_bfloat16* whi = g_cwhi + sub * 36864;
        const __nv_bfloat16* wlo = g_cwlo + sub * 36864;
        wmma::fragment<wmma::accumulator, 16, 16, 16, float> acc[2][4];
#pragma unroll
        for (int i = 0; i < 2; i++)
#pragma unroll
            for (int j = 0; j < 4; j++) wmma::fill_fragment(acc[i][j], 0.f);
        for (int it = 0; it < 18; it++) {
            int idx = wg * 18 + it;
            int kk = idx >> 2, kt = idx & 3;
            int ky = kk / 3, kx = kk % 3;
            wmma::fragment<wmma::matrix_a, 16, 16, 16, __nv_bfloat16, wmma::row_major> ah[2], al[2];
#pragma unroll
            for (int i = 0; i < 2; i++) {
                int m = m0 + i * 16;
                int base = (((m >> 6) + ky) * 68 + (m & 63) + kx) * 72 + kt * 16;
                wmma::load_matrix_sync(ah[i], slH + base, 72);
                wmma::load_matrix_sync(al[i], slL + base, 72);
            }
#pragma unroll
            for (int jc = 0; jc < 2; jc++) {
                wmma::fragment<wmma::matrix_b, 16, 16, 16, __nv_bfloat16, wmma::row_major> bf[2];
#pragma unroll
                for (int j = 0; j < 2; j++)
                    wmma::load_matrix_sync(bf[j], whi + kk * 4096 + kt * 1024 + jc * 32 + j * 16, 64);
#pragma unroll
                for (int i = 0; i < 2; i++)
#pragma unroll
                    for (int j = 0; j < 2; j++) {
                        wmma::mma_sync(acc[i][jc * 2 + j], ah[i], bf[j], acc[i][jc * 2 + j]);
                        wmma::mma_sync(acc[i][jc * 2 + j], al[i], bf[j], acc[i][jc * 2 + j]);
                    }
#pragma unroll
                for (int j = 0; j < 2; j++)
                    wmma::load_matrix_sync(bf[j], wlo + kk * 4096 + kt * 1024 + jc * 32 + j * 16, 64);
#pragma unroll
                for (int i = 0; i < 2; i++)
#pragma unroll
                    for (int j = 0; j < 2; j++)
                        wmma::mma_sync(acc[i][jc * 2 + j], ah[i], bf[j], acc[i][jc * 2 + j]);
            }
        }
        __syncthreads();           /* slab reads done -> reuse as HF partials */
        float* HFp = (float*)sb + wg * 8704;   /* 128 x 68 per group */
#pragma unroll
        for (int i = 0; i < 2; i++)
#pragma unroll
            for (int j = 0; j < 4; j++)
                wmma::store_matrix_sync(HFp + (m0 + i * 16) * 68 + j * 16, acc[i][j], 68,
                                        wmma::mem_row_major);
    }
    __syncthreads();
    /* combine partials -> z in SMEM (ld 65) */
    {
        float* HF = (float*)sb;
        for (int e = tid; e < 8192; e += 256) {
            int dy = e >> 12, oc = (e >> 6) & 63, xx = e & 63;
            int t = dy * 64 + xx;
            Z[t * 65 + oc] = HF[t * 68 + oc] + HF[8704 + t * 68 + oc] + bs[oc];
        }
    }
    __syncthreads();
    /* LN from SMEM z -> X hi/lo */
    __nv_bfloat16* Xhi = (__nv_bfloat16*)sb;
    __nv_bfloat16* Xlo = (__nv_bfloat16*)(sb + 18432);
    float* HF = (float*)(sb + 36864);            /* ld 72 */
    __nv_bfloat16* A2hi = (__nv_bfloat16*)(sb + 36864);
    __nv_bfloat16* A2lo = (__nv_bfloat16*)(sb + 55296);
    if (tid < 128) {
        float xv[64];
        float mu = 0.f;
#pragma unroll
        for (int c = 0; c < 64; c++) { xv[c] = Z[tid * 65 + c]; mu += xv[c]; }
        mu *= (1.0f / 64.0f);
        float var = 0.f;
#pragma unroll
        for (int c = 0; c < 64; c++) { float d = xv[c] - mu; var += d * d; }
        float rs = rsqrtf(var * (1.0f / 64.0f) + 1e-5f);
#pragma unroll
        for (int c = 0; c < 64; c++) {
            float v = (xv[c] - mu) * rs * lnws[c] + lnbs[c];
            __nv_bfloat16 hi = __float2bfloat16(v);
            Xhi[tid * 72 + c] = hi;
            Xlo[tid * 72 + c] = __float2bfloat16(v - __bfloat162float(hi));
        }
    }
    __syncthreads();

    int mw = wid & 3, nw = wid >> 2;
    int m0 = mw * 32, n0 = nw * 32;
    wmma::fragment<wmma::accumulator, 16, 16, 16, float> acc2[2][2];
#pragma unroll
    for (int i = 0; i < 2; i++)
#pragma unroll
        for (int j = 0; j < 2; j++) wmma::fill_fragment(acc2[i][j], 0.0f);

    for (int h = 0; h < 4; h++) {
        /* GEMM1 quarter -> HF (ld 72) */
        {
            wmma::fragment<wmma::accumulator, 16, 16, 16, float> acc1[2][2];
#pragma unroll
            for (int i = 0; i < 2; i++)
#pragma unroll
                for (int j = 0; j < 2; j++) wmma::fill_fragment(acc1[i][j], 0.0f);
#pragma unroll
            for (int kt = 0; kt < 4; kt++) {
                wmma::fragment<wmma::matrix_a, 16, 16, 16, __nv_bfloat16, wmma::row_major> ah[2], al[2];
#pragma unroll
                for (int i = 0; i < 2; i++) {
                    wmma::load_matrix_sync(ah[i], Xhi + (m0 + i * 16) * 72 + kt * 16, 72);
                    wmma::load_matrix_sync(al[i], Xlo + (m0 + i * 16) * 72 + kt * 16, 72);
                }
                wmma::fragment<wmma::matrix_b, 16, 16, 16, __nv_bfloat16, wmma::row_major> bh[2], bl[2];
#pragma unroll
                for (int j = 0; j < 2; j++) {
                    wmma::load_matrix_sync(bh[j], g_w1hi + kt * 16 * 256 + h * 64 + n0 + j * 16, 256);
                    wmma::load_matrix_sync(bl[j], g_w1lo + kt * 16 * 256 + h * 64 + n0 + j * 16, 256);
                }
#pragma unroll
                for (int i = 0; i < 2; i++)
#pragma unroll
                    for (int j = 0; j < 2; j++) {
                        wmma::mma_sync(acc1[i][j], ah[i], bh[j], acc1[i][j]);
                        wmma::mma_sync(acc1[i][j], al[i], bh[j], acc1[i][j]);
                        wmma::mma_sync(acc1[i][j], ah[i], bl[j], acc1[i][j]);
                    }
            }
#pragma unroll
            for (int i = 0; i < 2; i++)
#pragma unroll
                for (int j = 0; j < 2; j++)
                    wmma::store_matrix_sync(HF + (m0 + i * 16) * 72 + n0 + j * 16,
                                            acc1[i][j], 72, wmma::mem_row_major);
        }
        __syncthreads();
        /* gelu with A2 overlaying HF: stash reads to registers first */
        {
            float hv[32];
#pragma unroll
            for (int q = 0; q < 32; q++) {
                int p = tid + q * 256;
                hv[q] = HF[(p >> 6) * 72 + (p & 63)];
            }
            __syncthreads();
#pragma unroll
            for (int q = 0; q < 32; q++) {
                int p = tid + q * 256;
                int t = p >> 6, n = p & 63;
                float g = fast_gelu(hv[q] + b1s[h * 64 + n]);
                __nv_bfloat16 hi = __float2bfloat16(g);
                A2hi[t * 72 + n] = hi;
                A2lo[t * 72 + n] = __float2bfloat16(g - __bfloat162float(hi));
            }
        }
        __syncthreads();
        /* GEMM2 partial -> acc2 registers */
#pragma unroll
        for (int kt = 0; kt < 4; kt++) {
            wmma::fragment<wmma::matrix_a, 16, 16, 16, __nv_bfloat16, wmma::row_major> ah[2], al[2];
#pragma unroll
            for (int i = 0; i < 2; i++) {
                wmma::load_matrix_sync(ah[i], A2hi + (m0 + i * 16) * 72 + kt * 16, 72);
                wmma::load_matrix_sync(al[i], A2lo + (m0 + i * 16) * 72 + kt * 16, 72);
            }
            wmma::fragment<wmma::matrix_b, 16, 16, 16, __nv_bfloat16, wmma::row_major> bh[2], bl[2];
#pragma unroll
            for (int j = 0; j < 2; j++) {
                wmma::load_matrix_sync(bh[j], g_w2hi + (h * 64 + kt * 16) * 64 + n0 + j * 16, 64);
                wmma::load_matrix_sync(bl[j], g_w2lo + (h * 64 + kt * 16) * 64 + n0 + j * 16, 64);
            }
#pragma unroll
            for (int i = 0; i < 2; i++)
#pragma unroll
                for (int j = 0; j < 2; j++) {
                    wmma::mma_sync(acc2[i][j], ah[i], bh[j], acc2[i][j]);
                    wmma::mma_sync(acc2[i][j], al[i], bh[j], acc2[i][j]);
                    wmma::mma_sync(acc2[i][j], ah[i], bl[j], acc2[i][j]);
                }
        }
        __syncthreads();    /* A2 reads done before next GEMM1 overwrites HF */
    }
#pragma unroll
    for (int i = 0; i < 2; i++)
#pragma unroll
        for (int j = 0; j < 2; j++)
            wmma::store_matrix_sync(HF + (m0 + i * 16) * 72 + n0 + j * 16,
                                    acc2[i][j], 72, wmma::mem_row_major);
    __syncthreads();

    /* residual + writeout to g_fs tile layout */
    {
        float* op = g_fs + ((long)(sub * 512 + b * 128 + y0)) * 8192 + x0;
        for (int e = tid; e < 8192; e += 256) {
            int c = e >> 7, t = e & 127;
            int dy = t >> 6, xx = t & 63;
            op[dy * 8192 + c * 128 + xx] = Z[t * 65 + c] + HF[t * 72 + c] + b2s[c];
        }
    }
}

/* ====== K7: fused 1x1 fusion conv + LN + FFN + residual, 64-tok tiles ==== */
#define FZ_XHI  0
#define FZ_XLO  9216
#define FZ_HF0  18432
#define FZ_HF1  35840
#define FZ_A2HI 53248
#define FZ_A2LO 62464
#define FZ_CST  71680
#define FZ_Z    73728
#define FZ_AH   0
#define FZ_AL   33792
#define FZ_SMEM (73728 + 17408 + 128)

__global__ void __launch_bounds__(256, 2)
k_fuse_ffn(float* __restrict__ dout,
           const float* __restrict__ lnw, const float* __restrict__ lnb,
           const float* __restrict__ b1p, const float* __restrict__ b2p,
           const float* __restrict__ fb) {
    extern __shared__ char sb[];
    __nv_bfloat16* AH = (__nv_bfloat16*)(sb + FZ_AH);
    __nv_bfloat16* AL = (__nv_bfloat16*)(sb + FZ_AL);
    __nv_bfloat16* Xhi = (__nv_bfloat16*)(sb + FZ_XHI);
    __nv_bfloat16* Xlo = (__nv_bfloat16*)(sb + FZ_XLO);
    float* HF0 = (float*)(sb + FZ_HF0);
    float* HF1 = (float*)(sb + FZ_HF1);
    __nv_bfloat16* A2hi = (__nv_bfloat16*)(sb + FZ_A2HI);
    __nv_bfloat16* A2lo = (__nv_bfloat16*)(sb + FZ_A2LO);
    float* b1s = (float*)(sb + FZ_CST);
    float* b2s = b1s + 256;
    float* lnws = b2s + 64;
    float* lnbs = lnws + 64;
    float* fbs = lnbs + 64;
    float* Z = (float*)(sb + FZ_Z);

    int tid = threadIdx.x, wid = tid >> 5;
    int xh = blockIdx.x & 1, y = (blockIdx.x >> 1) & 127, b = blockIdx.x >> 8;
    int x0 = xh * 64;

    if (tid < 256) b1s[tid] = b1p[tid];
    if (tid < 64) {
        b2s[tid] = b2p[tid]; lnws[tid] = lnw[tid]; lnbs[tid] = lnb[tid]; fbs[tid] = fb[tid];
    }
    for (int p = tid; p < 16384; p += 256) {
        int k = p >> 6, x = p & 63;
        int s = k >> 6, c = k & 63;
        float v = g_fs[((long)(s * 512 + b * 128 + y)) * 8192 + c * 128 + x0 + x];
        __nv_bfloat16 hi = __float2bfloat16(v);
        AH[x * 264 + k] = hi;
        AL[x * 264 + k] = __float2bfloat16(v - __bfloat162float(hi));
    }
    __syncthreads();

    int wg = wid >> 2, ws = wid & 3;
    int m0 = (ws & 1) * 32, n0 = (ws >> 1) * 32;
    {
        wmma::fragment<wmma::accumulator, 16, 16, 16, float> acc[2][2];
#pragma unroll
        for (int i = 0; i < 2; i++)
#pragma unroll
            for (int j = 0; j < 2; j++) wmma::fill_fragment(acc[i][j], 0.f);
        for (int it = 0; it < 8; it++) {
            int kt = wg * 8 + it;
            wmma::fragment<wmma::matrix_a, 16, 16, 16, __nv_bfloat16, wmma::row_major> ah[2], al[2];
#pragma unroll
            for (int i = 0; i < 2; i++) {
                wmma::load_matrix_sync(ah[i], AH + (m0 + i * 16) * 264 + kt * 16, 264);
                wmma::load_matrix_sync(al[i], AL + (m0 + i * 16) * 264 + kt * 16, 264);
            }
            wmma::fragment<wmma::matrix_b, 16, 16, 16, __nv_bfloat16, wmma::row_major> bh[2], bl[2];
#pragma unroll
            for (int j = 0; j < 2; j++) {
                wmma::load_matrix_sync(bh[j], g_fwhi + kt * 1024 + n0 + j * 16, 64);
                wmma::load_matrix_sync(bl[j], g_fwlo + kt * 1024 + n0 + j * 16, 64);
            }
#pragma unroll
            for (int i = 0; i < 2; i++)
#pragma unroll
                for (int j = 0; j < 2; j++) {
                    wmma::mma_sync(acc[i][j], ah[i], bh[j], acc[i][j]);
                    wmma::mma_sync(acc[i][j], al[i], bh[j], acc[i][j]);
                    wmma::mma_sync(acc[i][j], ah[i], bl[j], acc[i][j]);
                }
        }
        __syncthreads();
        float* HFp = (wg == 0) ? HF0 : HF1;
#pragma unroll
        for (int i = 0; i < 2; i++)
#pragma unroll
            for (int j = 0; j < 2; j++)
                wmma::store_matrix_sync(HFp + (m0 + i * 16) * 68 + n0 + j * 16, acc[i][j], 68,
                                        wmma::mem_row_major);
    }
    __syncthreads();
    for (int e = tid; e < 4096; e += 256) {
        int t = e >> 6, c = e & 63;
        Z[t * 68 + c] = HF0[t * 68 + c] + HF1[t * 68 + c] + fbs[c];
    }
    __syncthreads();
    if (tid < 64) {
        float xv[64];
        float mu = 0.f;
#pragma unroll
        for (int c = 0; c < 64; c++) { xv[c] = Z[tid * 68 + c]; mu += xv[c]; }
        mu *= (1.0f / 64.0f);
        float var = 0.f;
#pragma unroll
        for (int c = 0; c < 64; c++) { float d = xv[c] - mu; var += d * d; }
        float rs = rsqrtf(var * (1.0f / 64.0f) + 1e-5f);
#pragma unroll
        for (int c = 0; c < 64; c++) {
            float v = (xv[c] - mu) * rs * lnws[c] + lnbs[c];
            __nv_bfloat16 hi = __float2bfloat16(v);
            Xhi[tid * 72 + c] = hi;
            Xlo[tid * 72 + c] = __float2bfloat16(v - __bfloat162float(hi));
        }
    }
    __syncthreads();

    wmma::fragment<wmma::accumulator, 16, 16, 16, float> acc2[2][2];
#pragma unroll
    for (int i = 0; i < 2; i++)
#pragma unroll
        for (int j = 0; j < 2; j++) wmma::fill_fragment(acc2[i][j], 0.0f);

    for (int h = 0; h < 4; h++) {
        {
            wmma::fragment<wmma::accumulator, 16, 16, 16, float> acc1[2][2];
#pragma unroll
            for (int i = 0; i < 2; i++)
#pragma unroll
                for (int j = 0; j < 2; j++) wmma::fill_fragment(acc1[i][j], 0.0f);
#pragma unroll
            for (int it = 0; it < 2; it++) {
                int kt = wg * 2 + it;
                wmma::fragment<wmma::matrix_a, 16, 16, 16, __nv_bfloat16, wmma::row_major> ah[2], al[2];
#pragma unroll
                for (int i = 0; i < 2; i++) {
                    wmma::load_matrix_sync(ah[i], Xhi + (m0 + i * 16) * 72 + kt * 16, 72);
                    wmma::load_matrix_sync(al[i], Xlo + (m0 + i * 16) * 72 + kt * 16, 72);
                }
                wmma::fragment<wmma::matrix_b, 16, 16, 16, __nv_bfloat16, wmma::row_major> bh[2], bl[2];
#pragma unroll
                for (int j = 0; j < 2; j++) {
                    wmma::load_matrix_sync(bh[j], g_w1hi + kt * 16 * 256 + h * 64 + n0 + j * 16, 256);
                    wmma::load_matrix_sync(bl[j], g_w1lo + kt * 16 * 256 + h * 64 + n0 + j * 16, 256);
                }
#pragma unroll
                for (int i = 0; i < 2; i++)
#pragma unroll
                    for (int j = 0; j < 2; j++) {
                        wmma::mma_sync(acc1[i][j], ah[i], bh[j], acc1[i][j]);
                        wmma::mma_sync(acc1[i][j], al[i], bh[j], acc1[i][j]);
                        wmma::mma_sync(acc1[i][j], ah[i], bl[j], acc1[i][j]);
                    }
            }
            float* HFp = (wg == 0) ? HF0 : HF1;
#pragma unroll
            for (int i = 0; i < 2; i++)
#pragma unroll
                for (int j = 0; j < 2; j++)
                    wmma::store_matrix_sync(HFp + (m0 + i * 16) * 68 + n0 + j * 16,
                                            acc1[i][j], 68, wmma::mem_row_major);
        }
        __syncthreads();
        for (int p = tid; p < 4096; p += 256) {
            int t = p >> 6, n = p & 63;
            float g = fast_gelu(HF0[t * 68 + n] + HF1[t * 68 + n] + b1s[h * 64 + n]);
            __nv_bfloat16 hi = __float2bfloat16(g);
            A2hi[t * 72 + n] = hi;
            A2lo[t * 72 + n] = __float2bfloat16(g - __bfloat162float(hi));
        }
        __syncthreads();
#pragma unroll
        for (int it = 0; it < 2; it++) {
            int kt = wg * 2 + it;
            wmma::fragment<wmma::matrix_a, 16, 16, 16, __nv_bfloat16, wmma::row_major> ah[2], al[2];
#pragma unroll
            for (int i = 0; i < 2; i++) {
                wmma::load_matrix_sync(ah[i], A2hi + (m0 + i * 16) * 72 + kt * 16, 72);
                wmma::load_matrix_sync(al[i], A2lo + (m0 + i * 16) * 72 + kt * 16, 72);
            }
            wmma::fragment<wmma::matrix_b, 16, 16, 16, __nv_bfloat16, wmma::row_major> bh[2], bl[2];
#pragma unroll
            for (int j = 0; j < 2; j++) {
                wmma::load_matrix_sync(bh[j], g_w2hi + (h * 64 + kt * 16) * 64 + n0 + j * 16, 64);
                wmma::load_matrix_sync(bl[j], g_w2lo + (h * 64 + kt * 16) * 64 + n0 + j * 16, 64);
            }
#pragma unroll
            for (int i = 0; i < 2; i++)
#pragma unroll
                for (int j = 0; j < 2; j++) {
                    wmma::mma_sync(acc2[i][j], ah[i], bh[j], acc2[i][j]);
                    wmma::mma_sync(acc2[i][j], al[i], bh[j], acc2[i][j]);
                    wmma::mma_sync(acc2[i][j], ah[i], bl[j], acc2[i][j]);
                }
        }
        __syncthreads();
    }
    {
        float* HFp = (wg == 0) ? HF0 : HF1;
#pragma unroll
        for (int i = 0; i < 2; i++)
#pragma unroll
            for (int j = 0; j < 2; j++)
                wmma::store_matrix_sync(HFp + (m0 + i * 16) * 68 + n0 + j * 16,
                                        acc2[i][j], 68, wmma::mem_row_major);
    }
    __syncthreads();
    for (int e = tid; e < 4096; e += 256) {
        int c = e >> 6, t = e & 63;
        dout[((long)(b * 64 + c)) * PIX + y * 128 + x0 + t] =
            Z[t * 68 + c] + HF0[t * 68 + c] + HF1[t * 68 + c] + b2s[c];
    }
}

/* ---------------- launch ---------------- */
extern "C" void kernel_launch(void* const* d_in, const int* in_sizes, int n_in,
                              void* d_out, int out_size) {
    const float* R      = (const float*)d_in[0];
    const float* off_w1 = (const float*)d_in[1];
    const float* off_b1 = (const float*)d_in[2];
    const float* off_w2 = (const float*)d_in[3];
    const float* off_b2 = (const float*)d_in[4];
    const float* w_ll   = (const float*)d_in[5];
    const float* b_ll   = (const float*)d_in[6];
    const float* w_lh   = (const float*)d_in[7];
    const float* b_lh   = (const float*)d_in[8];
    const float* w_hl   = (const float*)d_in[9];
    const float* b_hl   = (const float*)d_in[10];
    const float* w_hh   = (const float*)d_in[11];
    const float* b_hh   = (const float*)d_in[12];
    const float* ln_w   = (const float*)d_in[13];
    const float* ln_b   = (const float*)d_in[14];
    const float* ffn_w1 = (const float*)d_in[15];
    const float* ffn_b1 = (const float*)d_in[16];
    const float* ffn_w2 = (const float*)d_in[17];
    const float* ffn_b2 = (const float*)d_in[18];
    const float* fus_w  = (const float*)d_in[19];
    const float* fus_b  = (const float*)d_in[20];
    float* out = (float*)d_out;

    cudaFuncSetAttribute(k_off1_mma, cudaFuncAttributeMaxDynamicSharedMemorySize, S2_SMEM);
    cudaFuncSetAttribute(k_conv_ffn, cudaFuncAttributeMaxDynamicSharedMemorySize, CF_SMEM);
    cudaFuncSetAttribute(k_fuse_ffn, cudaFuncAttributeMaxDynamicSharedMemorySize, FZ_SMEM);

    k_prep<<<840, 256>>>(ffn_w1, ffn_w2, w_ll, w_lh, w_hl, w_hh, off_w1, fus_w);
    k_dwt<<<NSUB / 256, 256>>>(R);
    k_off1_mma<<<2048, 256, S2_SMEM>>>(R, off_b1);
    k_conv_ffn<<<512, 256, CF_SMEM>>>(0, b_ll, b_lh, b_hl, b_hh,
                                      ln_w, ln_b, ffn_b1, ffn_b2);
    k_off2<<<NTOK / 256, 256>>>(off_w2, off_b2);
    k_deform<<<dim3(2048, 3), 256>>>();
    k_conv_ffn<<<1536, 256, CF_SMEM>>>(1, b_ll, b_lh, b_hl, b_hh,
                                       ln_w, ln_b, ffn_b1, ffn_b2);
    k_fuse_ffn<<<1024, 256, FZ_SMEM>>>(out, ln_w, ln_b, ffn_b1, ffn_b2, fus_b);
}